// round 7
// baseline (speedup 1.0000x reference)
#include <cuda_runtime.h>
#include <cstdint>

#define Bb  128
#define Tt  128
#define Hh  1024
#define N3  3072
#define Mm  16384          // B*T
#define BH  (Bb * Hh)
#define NBLK 128

// ---------------- device scratch (static globals; no allocation) ----------------
__device__ __align__(128) float    g_xp[(size_t)Mm * N3];      // 201 MB
__device__ __align__(128) uint16_t g_Ahi[(size_t)Mm * Hh];     // layer input / layer-1 seq (hi)
__device__ __align__(128) uint16_t g_Alo[(size_t)Mm * Hh];
__device__ __align__(128) uint16_t g_Wxhi[(size_t)N3 * Hh];
__device__ __align__(128) uint16_t g_Wxlo[(size_t)N3 * Hh];
__device__ __align__(128) uint16_t g_Whhi[(size_t)N3 * Hh];
__device__ __align__(128) uint16_t g_Whlo[(size_t)N3 * Hh];
__device__ __align__(128) uint16_t g_hhi[2 * BH];              // ping-pong hidden (hi)
__device__ __align__(128) uint16_t g_hlo[2 * BH];
__device__ unsigned g_bar_count;
__device__ unsigned g_bar_gen;

// ============================ helpers ============================
__device__ __forceinline__ uint32_t smem_u32(const void* p) {
    uint32_t a;
    asm("{ .reg .u64 t; cvta.to.shared.u64 t, %1; cvt.u32.u64 %0, t; }" : "=r"(a) : "l"(p));
    return a;
}
#define CPA(dst, src) asm volatile("cp.async.cg.shared.global [%0], [%1], 16;" :: "r"(dst), "l"(src))
#define CP_COMMIT()   asm volatile("cp.async.commit_group;" ::: "memory")

__device__ __forceinline__ void ldsm4(uint32_t* r, uint32_t addr) {
    asm volatile("ldmatrix.sync.aligned.m8n8.x4.shared.b16 {%0,%1,%2,%3}, [%4];"
        : "=r"(r[0]), "=r"(r[1]), "=r"(r[2]), "=r"(r[3]) : "r"(addr));
}
__device__ __forceinline__ void ldsm2(uint32_t* r, uint32_t addr) {
    asm volatile("ldmatrix.sync.aligned.m8n8.x2.shared.b16 {%0,%1}, [%2];"
        : "=r"(r[0]), "=r"(r[1]) : "r"(addr));
}
__device__ __forceinline__ void mma_bf16(float* c, const uint32_t* a, const uint32_t* b) {
    asm volatile(
        "mma.sync.aligned.m16n8k16.row.col.f32.bf16.bf16.f32 "
        "{%0,%1,%2,%3}, {%4,%5,%6,%7}, {%8,%9}, {%0,%1,%2,%3};"
        : "+f"(c[0]), "+f"(c[1]), "+f"(c[2]), "+f"(c[3])
        : "r"(a[0]), "r"(a[1]), "r"(a[2]), "r"(a[3]), "r"(b[0]), "r"(b[1]));
}
__device__ __forceinline__ void split2(float a, float b, uint32_t& hi, uint32_t& lo) {
    asm("cvt.rn.bf16x2.f32 %0, %1, %2;" : "=r"(hi) : "f"(b), "f"(a));
    float ah = __uint_as_float(hi << 16);
    float bh = __uint_as_float(hi & 0xffff0000u);
    float ra = a - ah, rb = b - bh;
    asm("cvt.rn.bf16x2.f32 %0, %1, %2;" : "=r"(lo) : "f"(rb), "f"(ra));
}

// ---------------- fp32 -> (hi, lo) bf16 split, vectorized ----------------
__global__ void split_kernel(const float* __restrict__ src,
                             uint16_t* __restrict__ hi, uint16_t* __restrict__ lo, int n4) {
    int i = blockIdx.x * blockDim.x + threadIdx.x;
    if (i >= n4) return;
    float4 v = ((const float4*)src)[i];
    uint32_t h0, l0, h1, l1;
    split2(v.x, v.y, h0, l0);
    split2(v.z, v.w, h1, l1);
    ((uint2*)hi)[i] = make_uint2(h0, h1);
    ((uint2*)lo)[i] = make_uint2(l0, l1);
}

// ============ bulk GEMM (HMMA): unchanged from R5 (works, ~validated) ============
__global__ __launch_bounds__(256, 1) void gemm_mma(
    const uint16_t* __restrict__ Ahi, const uint16_t* __restrict__ Alo,
    const uint16_t* __restrict__ Whi, const uint16_t* __restrict__ Wlo,
    const float* __restrict__ bias, float* __restrict__ C)
{
    __shared__ __align__(16) uint8_t sm[2][4][4096];
    __shared__ float s_bias[128];
    const int tid = threadIdx.x, lane = tid & 31, wid = tid >> 5;
    const int m0 = blockIdx.y * 128, n0 = blockIdx.x * 128;
    const int wm = wid >> 2, wn = wid & 3;

    if (tid < 128) s_bias[tid] = bias[n0 + tid];

    const int lrow = tid >> 1, lc = tid & 1;
    const uint32_t ld_off = (uint32_t)(lrow * 32 + ((lc ^ ((lrow >> 2) & 1)) * 16));
    const uint32_t sb = smem_u32(sm);
    const uint16_t* pAh = Ahi + (size_t)(m0 + lrow) * Hh + lc * 8;
    const uint16_t* pAl = Alo + (size_t)(m0 + lrow) * Hh + lc * 8;
    const uint16_t* pWh = Whi + (size_t)(n0 + lrow) * Hh + lc * 8;
    const uint16_t* pWl = Wlo + (size_t)(n0 + lrow) * Hh + lc * 8;

    const int arow = wm * 64 + (lane & 7) + ((lane >> 3) & 1) * 8;
    const int ac = lane >> 4;
    const uint32_t aOff = (uint32_t)(arow * 32 + ((ac ^ ((arow >> 2) & 1)) * 16));
    const int brow = wn * 32 + ((lane >> 4) & 1) * 8 + (lane & 7);
    const int bc = (lane >> 3) & 1;
    const uint32_t bOff = (uint32_t)(brow * 32 + ((bc ^ ((brow >> 2) & 1)) * 16));

    float acc[4][4][4];
#pragma unroll
    for (int mi = 0; mi < 4; mi++)
#pragma unroll
        for (int ni = 0; ni < 4; ni++)
#pragma unroll
            for (int j = 0; j < 4; j++) acc[mi][ni][j] = 0.f;

    auto issue = [&](int s) {
        uint32_t d = sb + (uint32_t)((s & 1) * 16384);
        int go = s * 16;
        CPA(d + 0 * 4096 + ld_off, pAh + go);
        CPA(d + 1 * 4096 + ld_off, pAl + go);
        CPA(d + 2 * 4096 + ld_off, pWh + go);
        CPA(d + 3 * 4096 + ld_off, pWl + go);
        CP_COMMIT();
    };
    issue(0);

    for (int s = 0; s < 64; s++) {
        if (s < 63) { issue(s + 1); asm volatile("cp.async.wait_group 1;" ::: "memory"); }
        else        { asm volatile("cp.async.wait_group 0;" ::: "memory"); }
        __syncthreads();
        const uint32_t st = sb + (uint32_t)((s & 1) * 16384);
        uint32_t ah[4][4], al[4][4], bh[4][2], bl[4][2];
#pragma unroll
        for (int mi = 0; mi < 4; mi++) {
            ldsm4(ah[mi], st + 0 * 4096 + aOff + mi * 512);
            ldsm4(al[mi], st + 1 * 4096 + aOff + mi * 512);
        }
#pragma unroll
        for (int p = 0; p < 2; p++) {
            uint32_t r[4];
            ldsm4(r, st + 2 * 4096 + bOff + p * 512);
            bh[2 * p][0] = r[0]; bh[2 * p][1] = r[1]; bh[2 * p + 1][0] = r[2]; bh[2 * p + 1][1] = r[3];
            ldsm4(r, st + 3 * 4096 + bOff + p * 512);
            bl[2 * p][0] = r[0]; bl[2 * p][1] = r[1]; bl[2 * p + 1][0] = r[2]; bl[2 * p + 1][1] = r[3];
        }
#pragma unroll
        for (int mi = 0; mi < 4; mi++)
#pragma unroll
            for (int ni = 0; ni < 4; ni++) {
                mma_bf16(acc[mi][ni], ah[mi], bh[ni]);
                mma_bf16(acc[mi][ni], ah[mi], bl[ni]);
                mma_bf16(acc[mi][ni], al[mi], bh[ni]);
            }
        __syncthreads();
    }

    const int g = lane >> 2, tg2 = (lane & 3) * 2;
#pragma unroll
    for (int mi = 0; mi < 4; mi++) {
        const int mb = m0 + wm * 64 + mi * 16;
#pragma unroll
        for (int ni = 0; ni < 4; ni++) {
            const int nl = wn * 32 + ni * 8 + tg2;
            const float b0v = s_bias[nl], b1v = s_bias[nl + 1];
            float2 v0 = make_float2(acc[mi][ni][0] + b0v, acc[mi][ni][1] + b1v);
            float2 v1 = make_float2(acc[mi][ni][2] + b0v, acc[mi][ni][3] + b1v);
            *(float2*)&C[(size_t)(mb + g) * N3 + n0 + nl] = v0;
            *(float2*)&C[(size_t)(mb + g + 8) * N3 + n0 + nl] = v1;
        }
    }
}

// ============ persistent GRU: one launch per layer, all 128 timesteps ============
// 128 blocks; block owns 8 o-channels x 3 gates (24 Wh rows resident in SMEM, 96 KB).
// 8 warps = m16 batch slices; warp-private cp.async staging of h (3-stage, L2-only).
// Grid barrier between steps; recurrent state (hprev f32) lives in registers.
__global__ __launch_bounds__(256, 1) void gru_persist(
    const float* __restrict__ xp,
    const uint16_t* __restrict__ Whhi, const uint16_t* __restrict__ Whlo,
    const float* __restrict__ bh, const float* __restrict__ h0,
    uint16_t* __restrict__ hhi, uint16_t* __restrict__ hlo,       // [2*BH] ping-pong
    uint16_t* __restrict__ seq_hi, uint16_t* __restrict__ seq_lo, // layer0 else null
    float* __restrict__ seq_f32,                                  // layer1 else null
    float* __restrict__ last_out)
{
    extern __shared__ __align__(16) uint8_t dsm[];
    // [0, 98304): resident W: [hi|lo] x [kt 64][row 24][32B], chunk swizzle c^((row>>2)&1)
    // [98304, 147456): A staging: 8 warps x 3 stages x (hi 1KB | lo 1KB)
    const int tid = threadIdx.x, lane = tid & 31, wid = tid >> 5;
    const int o0 = blockIdx.x * 8;
    const uint32_t sB = smem_u32(dsm);
    const uint32_t sA0 = sB + 98304u + (uint32_t)wid * 6144u;
    __shared__ unsigned s_base;

    // ---- load resident weights (once) ----
    for (int i = tid; i < 6144; i += 256) {
        int half = i >> 11;          // /3072? no: 6144/2 = 3072 -> use explicit
        half = i / 3072;
        int rem = i % 3072;
        int kt = rem / 48;
        int r2 = rem % 48;
        int row = r2 >> 1, c = r2 & 1;
        int g = row >> 3, j = row & 7;
        const uint16_t* src = (half ? Whlo : Whhi) + (size_t)(g * Hh + o0 + j) * Hh + kt * 16 + c * 8;
        uint32_t dst = sB + (uint32_t)(half * 49152 + kt * 768 + row * 32 + ((c ^ ((row >> 2) & 1)) * 16));
        CPA(dst, src);
    }
    CP_COMMIT();
    asm volatile("cp.async.wait_group 0;" ::: "memory");
    if (tid == 0) s_base = *((volatile unsigned*)&g_bar_gen);
    __syncthreads();
    const unsigned base = s_base;

    // ldmatrix lane addressing
    const int arow = (lane & 7) + ((lane >> 3) & 1) * 8;
    const int ac = lane >> 4;
    const uint32_t aOff = (uint32_t)(arow * 32 + ((ac ^ ((arow >> 2) & 1)) * 16));
    const int brow = ((lane >> 4) & 1) * 8 + (lane & 7);
    const int bc = (lane >> 3) & 1;
    const uint32_t bOff = (uint32_t)(brow * 32 + ((bc ^ ((brow >> 2) & 1)) * 16));
    const int brow2 = 16 + (lane & 7);
    const uint32_t bOff2 = (uint32_t)(brow2 * 32 + ((bc ^ ((brow2 >> 2) & 1)) * 16));

    // per-lane output mapping: (m = m_l, m_l+8) x (o = o0+oq, +1)
    const int m_l = lane >> 2;
    const int b0w = wid * 16;
    const int oq = (lane & 3) * 2;
    const int o = o0 + oq;

    float bhv[3][2];
#pragma unroll
    for (int g = 0; g < 3; g++) {
        bhv[g][0] = bh[g * Hh + o];
        bhv[g][1] = bh[g * Hh + o + 1];
    }
    float hprev[2][2];
#pragma unroll
    for (int mi = 0; mi < 2; mi++) {
        hprev[mi][0] = h0[(size_t)(b0w + m_l + mi * 8) * Hh + o];
        hprev[mi][1] = h0[(size_t)(b0w + m_l + mi * 8) * Hh + o + 1];
    }

    // A-staging cp.async lane mapping: lane -> (ks = lane>>4, m = lane&15), 2 chunks + lo
    const int lks = lane >> 4, lm = lane & 15;
    const uint32_t sw0 = (uint32_t)(((lm >> 2) & 1) * 16);
    const uint32_t sw1 = sw0 ^ 16u;
    const uint32_t aDst = (uint32_t)(lks * 512 + lm * 32);

    for (int t = 0; t < Tt; t++) {
        const uint16_t* hin_hi = hhi + (size_t)(t & 1) * BH;
        const uint16_t* hin_lo = hlo + (size_t)(t & 1) * BH;

        // xp prefetch for this step
        float xg[3][2][2];
#pragma unroll
        for (int g = 0; g < 3; g++)
#pragma unroll
            for (int mi = 0; mi < 2; mi++) {
                float2 v = *(const float2*)&xp[((size_t)(b0w + m_l + mi * 8) * Tt + t) * N3 + g * Hh + o];
                xg[g][mi][0] = v.x; xg[g][mi][1] = v.y;
            }

        auto issueA = [&](int s) {
            uint32_t buf = sA0 + (uint32_t)((s % 3) * 2048);
            size_t row = (size_t)(b0w + lm) * Hh + s * 32 + lks * 16;
            const uint16_t* sh = hin_hi + row;
            const uint16_t* sl = hin_lo + row;
            uint32_t d = buf + aDst;
            CPA(d + sw0, sh);
            CPA(d + sw1, sh + 8);
            CPA(d + 1024 + sw0, sl);
            CPA(d + 1024 + sw1, sl + 8);
            CP_COMMIT();
        };

        float acc[3][4];
#pragma unroll
        for (int g = 0; g < 3; g++)
#pragma unroll
            for (int j = 0; j < 4; j++) acc[g][j] = 0.f;

        issueA(0);
        issueA(1);
        for (int s = 0; s < 32; s++) {
            if (s < 30) { issueA(s + 2); asm volatile("cp.async.wait_group 2;" ::: "memory"); }
            else if (s == 30) { asm volatile("cp.async.wait_group 1;" ::: "memory"); }
            else { asm volatile("cp.async.wait_group 0;" ::: "memory"); }
            __syncwarp();
            const uint32_t st = sA0 + (uint32_t)((s % 3) * 2048);
#pragma unroll
            for (int kt2 = 0; kt2 < 2; kt2++) {
                uint32_t ah[4], al[4];
                ldsm4(ah, st + kt2 * 512 + aOff);
                ldsm4(al, st + 1024 + kt2 * 512 + aOff);
                const uint32_t bhB = sB + (uint32_t)((s * 2 + kt2) * 768);
                const uint32_t blB = bhB + 49152u;
                uint32_t bh01[4], bh2[2], bl01[4], bl2[2];
                ldsm4(bh01, bhB + bOff);
                ldsm2(bh2, bhB + bOff2);
                ldsm4(bl01, blB + bOff);
                ldsm2(bl2, blB + bOff2);
                mma_bf16(acc[0], ah, &bh01[0]);
                mma_bf16(acc[0], ah, &bl01[0]);
                mma_bf16(acc[0], al, &bh01[0]);
                mma_bf16(acc[1], ah, &bh01[2]);
                mma_bf16(acc[1], ah, &bl01[2]);
                mma_bf16(acc[1], al, &bh01[2]);
                mma_bf16(acc[2], ah, bh2);
                mma_bf16(acc[2], ah, bl2);
                mma_bf16(acc[2], al, bh2);
            }
            __syncwarp();
        }

        // gates (all in registers)
        uint16_t* hho = hhi + (size_t)((t + 1) & 1) * BH;
        uint16_t* hlo_o = hlo + (size_t)((t + 1) & 1) * BH;
#pragma unroll
        for (int mi = 0; mi < 2; mi++) {
            float hn2[2];
#pragma unroll
            for (int oj = 0; oj < 2; oj++) {
                int j = mi * 2 + oj;
                float r = 1.f / (1.f + expf(-(xg[0][mi][oj] + acc[0][j] + bhv[0][oj])));
                float z = 1.f / (1.f + expf(-(xg[1][mi][oj] + acc[1][j] + bhv[1][oj])));
                float n = tanhf(xg[2][mi][oj] + r * (acc[2][j] + bhv[2][oj]));
                float hn = (1.f - z) * n + z * hprev[mi][oj];
                hprev[mi][oj] = hn;
                hn2[oj] = hn;
            }
            const int b = b0w + m_l + mi * 8;
            uint32_t hiw, low;
            split2(hn2[0], hn2[1], hiw, low);
            __stcg((uint32_t*)(hho + (size_t)b * Hh + o), hiw);
            __stcg((uint32_t*)(hlo_o + (size_t)b * Hh + o), low);
            if (seq_hi) {
                const size_t sr = ((size_t)b * Tt + t) * Hh + o;
                __stcg((uint32_t*)(seq_hi + sr), hiw);
                __stcg((uint32_t*)(seq_lo + sr), low);
            }
            if (seq_f32)
                *(float2*)&seq_f32[((size_t)b * Tt + t) * Hh + o] = make_float2(hn2[0], hn2[1]);
            if (t == Tt - 1)
                *(float2*)&last_out[(size_t)b * Hh + o] = make_float2(hn2[0], hn2[1]);
        }

        // grid barrier
        __threadfence();
        __syncthreads();
        if (tid == 0) {
            unsigned my = atomicAdd(&g_bar_count, 1u);
            unsigned tgt = base + (unsigned)t + 1u;
            if (my == NBLK - 1u) {
                atomicExch(&g_bar_count, 0u);
                __threadfence();
                atomicExch(&g_bar_gen, tgt);
            } else {
                while ((int)(*((volatile unsigned*)&g_bar_gen) - tgt) < 0) { }
            }
        }
        __syncthreads();
    }
}

// ---------------- launch ----------------
extern "C" void kernel_launch(void* const* d_in, const int* in_sizes, int n_in,
                              void* d_out, int out_size)
{
    const float* input       = (const float*)d_in[0];  // [B,T,H]
    const float* prev_hidden = (const float*)d_in[1];  // [L,B,H]
    const float* Wx          = (const float*)d_in[2];  // [L,3,H,H]
    const float* Wh          = (const float*)d_in[3];  // [L,3,H,H]
    const float* bx          = (const float*)d_in[4];  // [L,3,H]
    const float* bh          = (const float*)d_in[5];  // [L,3,H]
    float* out      = (float*)d_out;                   // [B,T,H] then [L,B,H]
    float* out_last = out + (size_t)Bb * Tt * Hh;

    static float*    p_xp = nullptr;
    static uint16_t *p_Ahi, *p_Alo, *p_Wxhi, *p_Wxlo, *p_Whhi, *p_Whlo, *p_hhi, *p_hlo;
    if (!p_xp) {
        cudaGetSymbolAddress((void**)&p_xp,   g_xp);
        cudaGetSymbolAddress((void**)&p_Ahi,  g_Ahi);
        cudaGetSymbolAddress((void**)&p_Alo,  g_Alo);
        cudaGetSymbolAddress((void**)&p_Wxhi, g_Wxhi);
        cudaGetSymbolAddress((void**)&p_Wxlo, g_Wxlo);
        cudaGetSymbolAddress((void**)&p_Whhi, g_Whhi);
        cudaGetSymbolAddress((void**)&p_Whlo, g_Whlo);
        cudaGetSymbolAddress((void**)&p_hhi,  g_hhi);
        cudaGetSymbolAddress((void**)&p_hlo,  g_hlo);
        cudaFuncSetAttribute(gru_persist, cudaFuncAttributeMaxDynamicSharedMemorySize, 147456);
    }

    const dim3 gGrid(N3 / 128, Mm / 128);   // (24, 128)

    // split layer-1 input activations
    {
        int n4 = (Mm * Hh) / 4;
        split_kernel<<<(n4 + 255) / 256, 256>>>(input, p_Ahi, p_Alo, n4);
    }

    for (int l = 0; l < 2; l++) {
        const int nw4 = (N3 * Hh) / 4;
        split_kernel<<<(nw4 + 255) / 256, 256>>>(Wx + (size_t)l * N3 * Hh, p_Wxhi, p_Wxlo, nw4);
        gemm_mma<<<gGrid, 256>>>(p_Ahi, p_Alo, p_Wxhi, p_Wxlo, bx + (size_t)l * N3, p_xp);

        split_kernel<<<(nw4 + 255) / 256, 256>>>(Wh + (size_t)l * N3 * Hh, p_Whhi, p_Whlo, nw4);
        {
            int n4 = BH / 4;   // h0 split into ping slot 0 (read by t=0)
            split_kernel<<<(n4 + 255) / 256, 256>>>(prev_hidden + (size_t)l * BH, p_hhi, p_hlo, n4);
        }

        uint16_t* shi = (l == 0) ? p_Ahi : nullptr;
        uint16_t* slo = (l == 0) ? p_Alo : nullptr;
        float*    sf  = (l == 1) ? out : nullptr;
        gru_persist<<<NBLK, 256, 147456>>>(p_xp, p_Whhi, p_Whlo,
                                           bh + (size_t)l * N3,
                                           prev_hidden + (size_t)l * BH,
                                           p_hhi, p_hlo, shi, slo, sf,
                                           out_last + (size_t)l * BH);
    }
}

// round 11
// speedup vs baseline: 1.1551x; 1.1551x over previous
#include <cuda_runtime.h>
#include <cstdint>

#define Bb  128
#define Tt  128
#define Hh  1024
#define N3  3072
#define Mm  16384          // B*T
#define BH  (Bb * Hh)

// ---------------- device scratch (static globals; no allocation) ----------------
__device__ __align__(128) float    g_xp[(size_t)Mm * N3];      // 201 MB
__device__ __align__(128) uint16_t g_Ahi[(size_t)Mm * Hh];     // layer input / layer-1 seq (hi)
__device__ __align__(128) uint16_t g_Alo[(size_t)Mm * Hh];
__device__ __align__(128) uint16_t g_Wxhi[(size_t)N3 * Hh];
__device__ __align__(128) uint16_t g_Wxlo[(size_t)N3 * Hh];
__device__ __align__(128) uint16_t g_Whhi[(size_t)N3 * Hh];
__device__ __align__(128) uint16_t g_Whlo[(size_t)N3 * Hh];
__device__ __align__(128) float    g_h[2][BH];
__device__ __align__(128) uint16_t g_hhi[2][BH];
__device__ __align__(128) uint16_t g_hlo[2][BH];

// ============================ helpers ============================
__device__ __forceinline__ uint32_t smem_u32(const void* p) {
    uint32_t a;
    asm("{ .reg .u64 t; cvta.to.shared.u64 t, %1; cvt.u32.u64 %0, t; }" : "=r"(a) : "l"(p));
    return a;
}
#define CPA(dst, src) asm volatile("cp.async.cg.shared.global [%0], [%1], 16;" :: "r"(dst), "l"(src))
#define CP_COMMIT()   asm volatile("cp.async.commit_group;" ::: "memory")

__device__ __forceinline__ void ldsm4(uint32_t* r, uint32_t addr) {
    asm volatile("ldmatrix.sync.aligned.m8n8.x4.shared.b16 {%0,%1,%2,%3}, [%4];"
        : "=r"(r[0]), "=r"(r[1]), "=r"(r[2]), "=r"(r[3]) : "r"(addr));
}
__device__ __forceinline__ void ldsm2(uint32_t* r, uint32_t addr) {
    asm volatile("ldmatrix.sync.aligned.m8n8.x2.shared.b16 {%0,%1}, [%2];"
        : "=r"(r[0]), "=r"(r[1]) : "r"(addr));
}
__device__ __forceinline__ void mma_bf16(float* c, const uint32_t* a, const uint32_t* b) {
    asm volatile(
        "mma.sync.aligned.m16n8k16.row.col.f32.bf16.bf16.f32 "
        "{%0,%1,%2,%3}, {%4,%5,%6,%7}, {%8,%9}, {%0,%1,%2,%3};"
        : "+f"(c[0]), "+f"(c[1]), "+f"(c[2]), "+f"(c[3])
        : "r"(a[0]), "r"(a[1]), "r"(a[2]), "r"(a[3]), "r"(b[0]), "r"(b[1]));
}
__device__ __forceinline__ void split2(float a, float b, uint32_t& hi, uint32_t& lo) {
    asm("cvt.rn.bf16x2.f32 %0, %1, %2;" : "=r"(hi) : "f"(b), "f"(a));
    float ah = __uint_as_float(hi << 16);
    float bh = __uint_as_float(hi & 0xffff0000u);
    float ra = a - ah, rb = b - bh;
    asm("cvt.rn.bf16x2.f32 %0, %1, %2;" : "=r"(lo) : "f"(rb), "f"(ra));
}
__device__ __forceinline__ void split1(float x, uint16_t& h, uint16_t& l) {
    uint32_t p, q;
    asm("cvt.rn.bf16x2.f32 %0, %1, %1;" : "=r"(p) : "f"(x));
    h = (uint16_t)(p & 0xffffu);
    float hf = __uint_as_float(p << 16);
    float r = x - hf;
    asm("cvt.rn.bf16x2.f32 %0, %1, %1;" : "=r"(q) : "f"(r));
    l = (uint16_t)(q & 0xffffu);
}

// ---------------- fp32 -> (hi, lo) bf16 split, vectorized ----------------
__global__ void split_kernel(const float* __restrict__ src,
                             uint16_t* __restrict__ hi, uint16_t* __restrict__ lo, int n4) {
    int i = blockIdx.x * blockDim.x + threadIdx.x;
    if (i >= n4) return;
    float4 v = ((const float4*)src)[i];
    uint32_t h0, l0, h1, l1;
    split2(v.x, v.y, h0, l0);
    split2(v.z, v.w, h1, l1);
    ((uint2*)hi)[i] = make_uint2(h0, h1);
    ((uint2*)lo)[i] = make_uint2(l0, l1);
}

// ============ bulk GEMM (HMMA): C[m,n] = sum_k A[m,k]*W[n,k] + bias[n] ============
// 128x128 tile, 4-stage cp.async pipeline (race-free with ONE sync/stage), 2 CTAs/SM.
__global__ __launch_bounds__(256, 2) void gemm_mma(
    const uint16_t* __restrict__ Ahi, const uint16_t* __restrict__ Alo,
    const uint16_t* __restrict__ Whi, const uint16_t* __restrict__ Wlo,
    const float* __restrict__ bias, float* __restrict__ C)
{
    extern __shared__ __align__(16) uint8_t sm[];   // 4 stages x [Ahi,Alo,Whi,Wlo] x 4096B = 64 KB
    __shared__ float s_bias[128];
    const int tid = threadIdx.x, lane = tid & 31, wid = tid >> 5;
    const int m0 = blockIdx.y * 128, n0 = blockIdx.x * 128;
    const int wm = wid >> 2, wn = wid & 3;

    if (tid < 128) s_bias[tid] = bias[n0 + tid];

    const int lrow = tid >> 1, lc = tid & 1;
    const uint32_t ld_off = (uint32_t)(lrow * 32 + ((lc ^ ((lrow >> 2) & 1)) * 16));
    const uint32_t sb = smem_u32(sm);
    const uint16_t* pAh = Ahi + (size_t)(m0 + lrow) * Hh + lc * 8;
    const uint16_t* pAl = Alo + (size_t)(m0 + lrow) * Hh + lc * 8;
    const uint16_t* pWh = Whi + (size_t)(n0 + lrow) * Hh + lc * 8;
    const uint16_t* pWl = Wlo + (size_t)(n0 + lrow) * Hh + lc * 8;

    const int arow = wm * 64 + (lane & 7) + ((lane >> 3) & 1) * 8;
    const int ac = lane >> 4;
    const uint32_t aOff = (uint32_t)(arow * 32 + ((ac ^ ((arow >> 2) & 1)) * 16));
    const int brow = wn * 32 + ((lane >> 4) & 1) * 8 + (lane & 7);
    const int bc = (lane >> 3) & 1;
    const uint32_t bOff = (uint32_t)(brow * 32 + ((bc ^ ((brow >> 2) & 1)) * 16));

    float acc[4][4][4];
#pragma unroll
    for (int mi = 0; mi < 4; mi++)
#pragma unroll
        for (int ni = 0; ni < 4; ni++)
#pragma unroll
            for (int j = 0; j < 4; j++) acc[mi][ni][j] = 0.f;

    auto issue = [&](int s) {
        uint32_t d = sb + (uint32_t)((s & 3) * 16384);
        int go = s * 16;
        CPA(d + 0 * 4096 + ld_off, pAh + go);
        CPA(d + 1 * 4096 + ld_off, pAl + go);
        CPA(d + 2 * 4096 + ld_off, pWh + go);
        CPA(d + 3 * 4096 + ld_off, pWl + go);
        CP_COMMIT();
    };
    issue(0);
    issue(1);

    for (int s = 0; s < 64; s++) {
        // issue(s+2) targets buf (s+2)&3, last read at iter s-2, separated by the
        // iter s-1 top-of-loop __syncthreads -> race-free with ONE sync per stage.
        if (s < 62) { issue(s + 2); asm volatile("cp.async.wait_group 2;" ::: "memory"); }
        else if (s == 62) { asm volatile("cp.async.wait_group 1;" ::: "memory"); }
        else { asm volatile("cp.async.wait_group 0;" ::: "memory"); }
        __syncthreads();

        const uint32_t st = sb + (uint32_t)((s & 3) * 16384);

        uint32_t bh[4][2], bl[4][2];
#pragma unroll
        for (int p = 0; p < 2; p++) {
            uint32_t r[4];
            ldsm4(r, st + 2 * 4096 + bOff + p * 512);
            bh[2 * p][0] = r[0]; bh[2 * p][1] = r[1]; bh[2 * p + 1][0] = r[2]; bh[2 * p + 1][1] = r[3];
            ldsm4(r, st + 3 * 4096 + bOff + p * 512);
            bl[2 * p][0] = r[0]; bl[2 * p][1] = r[1]; bl[2 * p + 1][0] = r[2]; bl[2 * p + 1][1] = r[3];
        }
#pragma unroll
        for (int mi = 0; mi < 4; mi++) {
            uint32_t ah[4], al[4];
            ldsm4(ah, st + 0 * 4096 + aOff + mi * 512);
            ldsm4(al, st + 1 * 4096 + aOff + mi * 512);
#pragma unroll
            for (int ni = 0; ni < 4; ni++) {
                mma_bf16(acc[mi][ni], ah, bh[ni]);
                mma_bf16(acc[mi][ni], ah, bl[ni]);
                mma_bf16(acc[mi][ni], al, bh[ni]);
            }
        }
    }

    const int g = lane >> 2, tg2 = (lane & 3) * 2;
#pragma unroll
    for (int mi = 0; mi < 4; mi++) {
        const int mb = m0 + wm * 64 + mi * 16;
#pragma unroll
        for (int ni = 0; ni < 4; ni++) {
            const int nl = wn * 32 + ni * 8 + tg2;
            const float b0v = s_bias[nl], b1v = s_bias[nl + 1];
            float2 v0 = make_float2(acc[mi][ni][0] + b0v, acc[mi][ni][1] + b1v);
            float2 v1 = make_float2(acc[mi][ni][2] + b0v, acc[mi][ni][3] + b1v);
            *(float2*)&C[(size_t)(mb + g) * N3 + n0 + nl] = v0;
            *(float2*)&C[(size_t)(mb + g + 8) * N3 + n0 + nl] = v1;
        }
    }
}

// ============ GRU step (HMMA): hp = h @ Wh^T for 64b x (16o x 3 gates), then gates ============
// R5 version, verbatim (known-good at 7250 us): grid (64, 2), 8 warps, k16 double-buffered.
__global__ __launch_bounds__(256, 1) void gru_mma(
    const float* __restrict__ xp,
    const uint16_t* __restrict__ Whhi, const uint16_t* __restrict__ Whlo,
    const float* __restrict__ bh,
    const float* __restrict__ h_f32_in,
    const uint16_t* __restrict__ h_hi_in, const uint16_t* __restrict__ h_lo_in,
    float* __restrict__ h_f32_out, uint16_t* __restrict__ h_hi_out, uint16_t* __restrict__ h_lo_out,
    float* __restrict__ seq_f32, uint16_t* __restrict__ seq_hi, uint16_t* __restrict__ seq_lo,
    float* __restrict__ last_out, int t)
{
    __shared__ __align__(16) uint8_t smA[2][2][2048];
    __shared__ __align__(16) uint8_t smB[2][2][1536];
    __shared__ float hp[48][69];
    const int tid = threadIdx.x, lane = tid & 31, wid = tid >> 5;
    const int o0 = blockIdx.x * 16, b0 = blockIdx.y * 64;
    const int wm = wid >> 1, wn = wid & 1;
    const uint32_t sA = smem_u32(smA), sB = smem_u32(smB);

    const int aHalf = tid >> 7, arw = (tid & 127) >> 1, acx = tid & 1;
    const uint32_t aDst = (uint32_t)(aHalf * 2048 + arw * 32 + ((acx ^ ((arw >> 2) & 1)) * 16));
    const uint16_t* aSrc = (aHalf ? h_lo_in : h_hi_in) + (size_t)(b0 + arw) * Hh + acx * 8;

    const bool bAct = tid < 192;
    const int u = tid < 96 ? tid : tid - 96;
    const int bHalf = tid >= 96 ? 1 : 0;
    const int brr = u >> 1, bcx = u & 1;
    const int bgx = brr >> 4, boo = brr & 15;
    const uint32_t bDst = (uint32_t)(bHalf * 1536 + brr * 32 + ((bcx ^ ((brr >> 2) & 1)) * 16));
    const uint16_t* bSrc = (bHalf ? Whlo : Whhi) + (size_t)(bgx * Hh + o0 + boo) * Hh + bcx * 8;

    const int arow = wm * 16 + (lane & 7) + ((lane >> 3) & 1) * 8;
    const int ac2 = lane >> 4;
    const uint32_t aOff = (uint32_t)(arow * 32 + ((ac2 ^ ((arow >> 2) & 1)) * 16));
    const int brow = wn * 24 + ((lane >> 4) & 1) * 8 + (lane & 7);
    const int bc2 = (lane >> 3) & 1;
    const uint32_t bOff = (uint32_t)(brow * 32 + ((bc2 ^ ((brow >> 2) & 1)) * 16));
    const int brow2 = wn * 24 + 16 + (lane & 7);
    const uint32_t bOff2 = (uint32_t)(brow2 * 32 + ((bc2 ^ ((brow2 >> 2) & 1)) * 16));

    float acc[3][4];
#pragma unroll
    for (int ni = 0; ni < 3; ni++)
#pragma unroll
        for (int j = 0; j < 4; j++) acc[ni][j] = 0.f;

    auto issue = [&](int s) {
        uint32_t st = (uint32_t)(s & 1);
        CPA(sA + st * 4096 + aDst, aSrc + s * 16);
        if (bAct) CPA(sB + st * 3072 + bDst, bSrc + s * 16);
        CP_COMMIT();
    };
    issue(0);

    for (int s = 0; s < 64; s++) {
        if (s < 63) { issue(s + 1); asm volatile("cp.async.wait_group 1;" ::: "memory"); }
        else        { asm volatile("cp.async.wait_group 0;" ::: "memory"); }
        __syncthreads();
        const uint32_t stA = sA + (uint32_t)((s & 1) * 4096);
        const uint32_t stB = sB + (uint32_t)((s & 1) * 3072);
        uint32_t ah[4], al[4], bhf[3][2], blf[3][2], r[4];
        ldsm4(ah, stA + aOff);
        ldsm4(al, stA + 2048 + aOff);
        ldsm4(r, stB + bOff);
        bhf[0][0] = r[0]; bhf[0][1] = r[1]; bhf[1][0] = r[2]; bhf[1][1] = r[3];
        ldsm2(bhf[2], stB + bOff2);
        ldsm4(r, stB + 1536 + bOff);
        blf[0][0] = r[0]; blf[0][1] = r[1]; blf[1][0] = r[2]; blf[1][1] = r[3];
        ldsm2(blf[2], stB + 1536 + bOff2);
#pragma unroll
        for (int ni = 0; ni < 3; ni++) {
            mma_bf16(acc[ni], ah, bhf[ni]);
            mma_bf16(acc[ni], ah, blf[ni]);
            mma_bf16(acc[ni], al, bhf[ni]);
        }
        __syncthreads();
    }

    const int g = lane >> 2, tg2 = (lane & 3) * 2;
#pragma unroll
    for (int ni = 0; ni < 3; ni++) {
        const int nb = wn * 24 + ni * 8 + tg2;
        const int mb = wm * 16;
        hp[nb][mb + g]         = acc[ni][0];
        hp[nb + 1][mb + g]     = acc[ni][1];
        hp[nb][mb + g + 8]     = acc[ni][2];
        hp[nb + 1][mb + g + 8] = acc[ni][3];
    }
    __syncthreads();

    const int o_l = tid & 15, bq = tid >> 4;
    const int o = o0 + o_l;
    const float bhr = bh[o], bhz = bh[Hh + o], bhn = bh[2 * Hh + o];
#pragma unroll
    for (int i = 0; i < 4; i++) {
        const int bl = bq * 4 + i;
        const int bg = b0 + bl;
        const float hr = hp[o_l][bl], hz = hp[16 + o_l][bl], hn = hp[32 + o_l][bl];
        const size_t xrow = ((size_t)bg * Tt + t) * N3;
        const float xr = xp[xrow + o], xz = xp[xrow + Hh + o], xn = xp[xrow + 2 * Hh + o];
        const float hprev = h_f32_in[(size_t)bg * Hh + o];
        const float rg = 1.f / (1.f + expf(-(xr + hr + bhr)));
        const float zg = 1.f / (1.f + expf(-(xz + hz + bhz)));
        const float ng = tanhf(xn + rg * (hn + bhn));
        const float hnew = (1.f - zg) * ng + zg * hprev;
        h_f32_out[(size_t)bg * Hh + o] = hnew;
        uint16_t hb, lb; split1(hnew, hb, lb);
        h_hi_out[(size_t)bg * Hh + o] = hb;
        h_lo_out[(size_t)bg * Hh + o] = lb;
        if (seq_hi) {
            const size_t sr = ((size_t)bg * Tt + t) * Hh + o;
            seq_hi[sr] = hb; seq_lo[sr] = lb;
        }
        if (seq_f32) seq_f32[((size_t)bg * Tt + t) * Hh + o] = hnew;
        if (last_out) last_out[(size_t)bg * Hh + o] = hnew;
    }
}

// ---------------- launch ----------------
extern "C" void kernel_launch(void* const* d_in, const int* in_sizes, int n_in,
                              void* d_out, int out_size)
{
    const float* input       = (const float*)d_in[0];  // [B,T,H]
    const float* prev_hidden = (const float*)d_in[1];  // [L,B,H]
    const float* Wx          = (const float*)d_in[2];  // [L,3,H,H]
    const float* Wh          = (const float*)d_in[3];  // [L,3,H,H]
    const float* bx          = (const float*)d_in[4];  // [L,3,H]
    const float* bh          = (const float*)d_in[5];  // [L,3,H]
    float* out      = (float*)d_out;                   // [B,T,H] then [L,B,H]
    float* out_last = out + (size_t)Bb * Tt * Hh;

    static float*    p_xp = nullptr;
    static uint16_t *p_Ahi, *p_Alo, *p_Wxhi, *p_Wxlo, *p_Whhi, *p_Whlo, *p_hhi, *p_hlo;
    static float*    p_h;
    if (!p_xp) {
        cudaGetSymbolAddress((void**)&p_xp,   g_xp);
        cudaGetSymbolAddress((void**)&p_Ahi,  g_Ahi);
        cudaGetSymbolAddress((void**)&p_Alo,  g_Alo);
        cudaGetSymbolAddress((void**)&p_Wxhi, g_Wxhi);
        cudaGetSymbolAddress((void**)&p_Wxlo, g_Wxlo);
        cudaGetSymbolAddress((void**)&p_Whhi, g_Whhi);
        cudaGetSymbolAddress((void**)&p_Whlo, g_Whlo);
        cudaGetSymbolAddress((void**)&p_h,    g_h);
        cudaGetSymbolAddress((void**)&p_hhi,  g_hhi);
        cudaGetSymbolAddress((void**)&p_hlo,  g_hlo);
        cudaFuncSetAttribute(gemm_mma, cudaFuncAttributeMaxDynamicSharedMemorySize, 65536);
    }

    const dim3 gGrid(N3 / 128, Mm / 128);   // (24, 128)
    const dim3 sGrid(Hh / 16, Bb / 64);     // (64, 2)

    // split layer-1 input activations
    {
        int n4 = (Mm * Hh) / 4;
        split_kernel<<<(n4 + 255) / 256, 256>>>(input, p_Ahi, p_Alo, n4);
    }

    for (int l = 0; l < 2; l++) {
        const int nw4 = (N3 * Hh) / 4;
        split_kernel<<<(nw4 + 255) / 256, 256>>>(Wx + (size_t)l * N3 * Hh, p_Wxhi, p_Wxlo, nw4);
        gemm_mma<<<gGrid, 256, 65536>>>(p_Ahi, p_Alo, p_Wxhi, p_Wxlo, bx + (size_t)l * N3, p_xp);

        split_kernel<<<(nw4 + 255) / 256, 256>>>(Wh + (size_t)l * N3 * Hh, p_Whhi, p_Whlo, nw4);
        {
            int n4 = BH / 4;   // h0 split into slot 1 (read by t=0)
            split_kernel<<<(n4 + 255) / 256, 256>>>(prev_hidden + (size_t)l * BH,
                                                    p_hhi + 1 * BH, p_hlo + 1 * BH, n4);
        }

        for (int t = 0; t < Tt; t++) {
            const int rs = (t + 1) & 1, ws = t & 1;
            const float* h_in_f32 = (t == 0) ? (prev_hidden + (size_t)l * BH) : (p_h + (size_t)rs * BH);
            float*    seqf = (l == 1) ? out : nullptr;
            uint16_t* shi  = (l == 0) ? p_Ahi : nullptr;
            uint16_t* slo  = (l == 0) ? p_Alo : nullptr;
            float*    last = (t == Tt - 1) ? (out_last + (size_t)l * BH) : nullptr;
            gru_mma<<<sGrid, 256>>>(p_xp, p_Whhi, p_Whlo, bh + (size_t)l * N3,
                                    h_in_f32, p_hhi + (size_t)rs * BH, p_hlo + (size_t)rs * BH,
                                    p_h + (size_t)ws * BH, p_hhi + (size_t)ws * BH, p_hlo + (size_t)ws * BH,
                                    seqf, shi, slo, last, t);
        }
    }
}